// round 10
// baseline (speedup 1.0000x reference)
#include <cuda_runtime.h>
#include <cuda_bf16.h>
#include <math.h>
#include <stdint.h>

#define S 2048
#define D 64
#define NH 32
#define SCALE 0.125f
#define STR 72            // Q/K smem row stride in bf16 (64 data + 8 pad)
#define VSTR 136          // Vt smem row stride in bf16 (128 data + 8 pad)

// per-(head, 128-wide k-tile, row) partial sums of exp(s)
__device__ float g_stats[(size_t)NH * 16 * S];
// split-K partial O over 256-wide k-pairs: [h][qt][p<8][128*64]
__device__ float g_part[(size_t)NH * 16 * 8 * 128 * 64];

// ------------------------------ helpers -----------------------------------
__device__ __forceinline__ uint32_t smem_u32(const void* p) {
    return (uint32_t)__cvta_generic_to_shared(p);
}
__device__ __forceinline__ void ldsm4(uint32_t* r, uint32_t addr) {
    asm volatile("ldmatrix.sync.aligned.m8n8.x4.shared.b16 {%0,%1,%2,%3}, [%4];"
                 : "=r"(r[0]), "=r"(r[1]), "=r"(r[2]), "=r"(r[3]) : "r"(addr));
}
__device__ __forceinline__ void ldsm2(uint32_t* r, uint32_t addr) {
    asm volatile("ldmatrix.sync.aligned.m8n8.x2.shared.b16 {%0,%1}, [%2];"
                 : "=r"(r[0]), "=r"(r[1]) : "r"(addr));
}
__device__ __forceinline__ void mma_bf16(float* c, const uint32_t* a, const uint32_t* b) {
    asm volatile("mma.sync.aligned.m16n8k16.row.col.f32.bf16.bf16.f32 "
                 "{%0,%1,%2,%3},{%4,%5,%6,%7},{%8,%9},{%0,%1,%2,%3};"
                 : "+f"(c[0]), "+f"(c[1]), "+f"(c[2]), "+f"(c[3])
                 : "r"(a[0]), "r"(a[1]), "r"(a[2]), "r"(a[3]), "r"(b[0]), "r"(b[1]));
}
__device__ __forceinline__ void split4(__nv_bfloat16* hi, __nv_bfloat16* lo,
                                       int off, float4 v) {
    __nv_bfloat16 h0 = __float2bfloat16(v.x), h1 = __float2bfloat16(v.y);
    __nv_bfloat16 h2 = __float2bfloat16(v.z), h3 = __float2bfloat16(v.w);
    __nv_bfloat16 l0 = __float2bfloat16(v.x - __bfloat162float(h0));
    __nv_bfloat16 l1 = __float2bfloat16(v.y - __bfloat162float(h1));
    __nv_bfloat16 l2 = __float2bfloat16(v.z - __bfloat162float(h2));
    __nv_bfloat16 l3 = __float2bfloat16(v.w - __bfloat162float(h3));
    uint2 hv = make_uint2((uint32_t)__bfloat16_as_ushort(h0) | ((uint32_t)__bfloat16_as_ushort(h1) << 16),
                          (uint32_t)__bfloat16_as_ushort(h2) | ((uint32_t)__bfloat16_as_ushort(h3) << 16));
    uint2 lv = make_uint2((uint32_t)__bfloat16_as_ushort(l0) | ((uint32_t)__bfloat16_as_ushort(l1) << 16),
                          (uint32_t)__bfloat16_as_ushort(l2) | ((uint32_t)__bfloat16_as_ushort(l3) << 16));
    *(uint2*)(hi + off) = hv;
    *(uint2*)(lo + off) = lv;
}
__device__ __forceinline__ uint32_t pk2(float a, float b) {
    __nv_bfloat162 h = __floats2bfloat162_rn(a, b);
    return *(uint32_t*)&h;
}

__device__ __forceinline__ void stage_q(const float* Qh, int q0, int t,
                                        __nv_bfloat16* Qhi, __nv_bfloat16* Qlo) {
    for (int e = t; e < 128 * 16; e += 256) {
        int r = e >> 4, c4 = e & 15;
        float4 q4 = *(const float4*)(Qh + (size_t)(q0 + r) * D + (c4 << 2));
        q4.x *= SCALE; q4.y *= SCALE; q4.z *= SCALE; q4.w *= SCALE;
        split4(Qhi, Qlo, r * STR + (c4 << 2), q4);
    }
}
__device__ __forceinline__ void stage_k(const float* Kh, int k0, int t,
                                        __nv_bfloat16* Khi, __nv_bfloat16* Klo) {
    for (int e = t; e < 128 * 16; e += 256) {
        int r = e >> 4, c4 = e & 15;
        float4 k4 = *(const float4*)(Kh + (size_t)(k0 + r) * D + (c4 << 2));
        split4(Khi, Klo, r * STR + (c4 << 2), k4);
    }
}

// full-precision QK^T (3 MMA), ldsm2-B pattern (best-profiled variant, R7)
__device__ __forceinline__ void qk_mma3(uint32_t qhiB, uint32_t qloB,
                                        uint32_t khiB, uint32_t kloB,
                                        int wr, int L, float acc[16][4]) {
#pragma unroll
    for (int kk = 0; kk < 4; kk++) {
        uint32_t ah[4], al[4];
        uint32_t aoff = (uint32_t)(((wr + (L & 15)) * STR + (kk << 4) + ((L >> 4) << 3)) << 1);
        ldsm4(ah, qhiB + aoff);
        ldsm4(al, qloB + aoff);
#pragma unroll
        for (int n = 0; n < 16; n++) {
            uint32_t boff = (uint32_t)((((n << 3) + (L & 7)) * STR +
                                        (kk << 4) + (((L >> 3) & 1) << 3)) << 1);
            uint32_t bh[2], bl[2];
            ldsm2(bh, khiB + boff);
            ldsm2(bl, kloB + boff);
            mma_bf16(acc[n], ah, bh);
            mma_bf16(acc[n], ah, bl);
            mma_bf16(acc[n], al, bh);
        }
    }
}

// full-precision QK^T (3 MMA), ldsm4-paired B (used in emit, where it helped)
__device__ __forceinline__ void qk_mma8(uint32_t qhiB, uint32_t qloB,
                                        uint32_t khiB, uint32_t kloB,
                                        int wr, int L, float acc[16][4]) {
#pragma unroll
    for (int kk = 0; kk < 4; kk++) {
        uint32_t ah[4], al[4];
        uint32_t aoff = (uint32_t)(((wr + (L & 15)) * STR + (kk << 4) + ((L >> 4) << 3)) << 1);
        ldsm4(ah, qhiB + aoff);
        ldsm4(al, qloB + aoff);
#pragma unroll
        for (int n2 = 0; n2 < 8; n2++) {
            uint32_t boff = (uint32_t)((((n2 << 4) + ((L >> 4) << 3) + (L & 7)) * STR +
                                        (kk << 4) + (((L >> 3) & 1) << 3)) << 1);
            uint32_t bh[4], bl[4];
            ldsm4(bh, khiB + boff);
            ldsm4(bl, kloB + boff);
            mma_bf16(acc[2 * n2],     ah, &bh[0]);
            mma_bf16(acc[2 * n2],     ah, &bl[0]);
            mma_bf16(acc[2 * n2],     al, &bh[0]);
            mma_bf16(acc[2 * n2 + 1], ah, &bh[2]);
            mma_bf16(acc[2 * n2 + 1], ah, &bl[2]);
            mma_bf16(acc[2 * n2 + 1], al, &bh[2]);
        }
    }
}

// ---------------------------------------------------------------------------
// K1: stats — full-precision QK per 256-wide k-pair, rowsums -> g_stats.
// ---------------------------------------------------------------------------
__global__ __launch_bounds__(256, 2)
void stats_mma(const float* __restrict__ Q, const float* __restrict__ Km) {
    int p = blockIdx.x, qt = 15 - blockIdx.y, h = blockIdx.z;
    int kt0 = p << 1;
    if (kt0 > qt) return;
    int q0 = qt << 7;
    int t = threadIdx.x;

    extern __shared__ char smraw[];
    __nv_bfloat16* Qhi = (__nv_bfloat16*)smraw;
    __nv_bfloat16* Qlo = Qhi + 128 * STR;
    __nv_bfloat16* Khi = Qlo + 128 * STR;
    __nv_bfloat16* Klo = Khi + 128 * STR;

    stage_q(Q + (size_t)h * S * D, q0, t, Qhi, Qlo);

    const float* Kh = Km + (size_t)h * S * D;
    int w = t >> 5, L = t & 31;
    int wr = w << 4;
    int g = L >> 2, q = L & 3;
    int gi0 = q0 + wr + g, gi1 = gi0 + 8;

#pragma unroll 1
    for (int sub = 0; sub < 2; sub++) {
        int kt = kt0 + sub;
        if (kt > qt) break;
        int k0 = kt << 7;
        __syncthreads();
        stage_k(Kh, k0, t, Khi, Klo);
        __syncthreads();

        float acc[16][4];
#pragma unroll
        for (int n = 0; n < 16; n++)
#pragma unroll
            for (int i = 0; i < 4; i++) acc[n][i] = 0.f;
        qk_mma3(smem_u32(Qhi), smem_u32(Qlo), smem_u32(Khi), smem_u32(Klo), wr, L, acc);

        float s0 = 0.f, s1 = 0.f;
        if (kt == qt) {
#pragma unroll
            for (int n = 0; n < 16; n++) {
                int cg = k0 + (n << 3) + (q << 1);
                s0 += ((cg > gi0) ? 0.f : __expf(acc[n][0])) +
                      ((cg + 1 > gi0) ? 0.f : __expf(acc[n][1]));
                s1 += ((cg > gi1) ? 0.f : __expf(acc[n][2])) +
                      ((cg + 1 > gi1) ? 0.f : __expf(acc[n][3]));
            }
        } else {
#pragma unroll
            for (int n = 0; n < 16; n++) {
                s0 += __expf(acc[n][0]) + __expf(acc[n][1]);
                s1 += __expf(acc[n][2]) + __expf(acc[n][3]);
            }
        }
        s0 += __shfl_xor_sync(0xffffffffu, s0, 1);
        s0 += __shfl_xor_sync(0xffffffffu, s0, 2);
        s1 += __shfl_xor_sync(0xffffffffu, s1, 1);
        s1 += __shfl_xor_sync(0xffffffffu, s1, 2);
        if (q == 0) {
            size_t sb = (size_t)(h * 16 + kt) * S;
            g_stats[sb + gi0] = s0;
            g_stats[sb + gi1] = s1;
        }
    }
}

// ---------------------------------------------------------------------------
// K2: emit — per (h, qt, 256-wide k-pair): recompute s (full precision),
// write final W = exp(s)*Linv once, fused PV; pair-partial O -> g_part.
// ---------------------------------------------------------------------------
__global__ __launch_bounds__(256, 2)
void emit_mma(const float* __restrict__ Q, const float* __restrict__ Km,
              const float* __restrict__ V, float* __restrict__ W) {
    int p = blockIdx.x, qt = 15 - blockIdx.y, h = blockIdx.z;
    int kt0 = p << 1;
    float* Wh = W + (size_t)h * S * S;
    int q0 = qt << 7;
    int t = threadIdx.x;

    if (kt0 > qt) {                      // both tiles masked: zero 256 cols
        float4 z = make_float4(0.f, 0.f, 0.f, 0.f);
        int c0 = kt0 << 7;
        for (int e = t; e < 128 * 64; e += 256) {
            int r = e >> 6, c4 = e & 63;
            __stcs((float4*)(Wh + (size_t)(q0 + r) * S + c0 + (c4 << 2)), z);
        }
        return;
    }

    extern __shared__ char smraw[];
    __nv_bfloat16* Qhi = (__nv_bfloat16*)smraw;
    __nv_bfloat16* Qlo = Qhi + 128 * STR;
    __nv_bfloat16* Khi = Qlo + 128 * STR;
    __nv_bfloat16* Klo = Khi + 128 * STR;
    __nv_bfloat16* Vthi = Khi;           // reused after QK mma
    __nv_bfloat16* Vtlo = Klo;
    __shared__ float Ls[128];
    __shared__ float Osm[128][68];

    const float* Vh = V + (size_t)h * S * D;

    if (t < 128) {
        float Lsum = 0.f;
        for (int k2 = 0; k2 <= qt; k2++)
            Lsum += g_stats[(size_t)(h * 16 + k2) * S + q0 + t];
        Ls[t] = 1.f / Lsum;
    }
    stage_q(Q + (size_t)h * S * D, q0, t, Qhi, Qlo);

    int w = t >> 5, L = t & 31;
    int wr = w << 4;
    int g = L >> 2, q = L & 3;
    int gi0 = q0 + wr + g, gi1 = gi0 + 8;
    uint32_t vhiB = smem_u32(Vthi), vloB = smem_u32(Vtlo);
    bool two = (kt0 + 1 <= qt);

    float acc_o[8][4];

#pragma unroll 1
    for (int sub = 0; sub < 2; sub++) {
        int kt = kt0 + sub;
        if (kt > qt) break;
        int k0 = kt << 7;
        __syncthreads();
        stage_k(Km + (size_t)h * S * D, k0, t, Khi, Klo);
        __syncthreads();

        float acc[16][4];
#pragma unroll
        for (int n = 0; n < 16; n++)
#pragma unroll
            for (int i = 0; i < 4; i++) acc[n][i] = 0.f;
        qk_mma8(smem_u32(Qhi), smem_u32(Qlo), smem_u32(Khi), smem_u32(Klo), wr, L, acc);
        __syncthreads();

        for (int e = t; e < 128 * 16; e += 256) {
            int j = e >> 4, d4 = e & 15;
            float4 v4 = *(const float4*)(Vh + (size_t)(k0 + j) * D + (d4 << 2));
            float vv[4] = {v4.x, v4.y, v4.z, v4.w};
#pragma unroll
            for (int i = 0; i < 4; i++) {
                int d = (d4 << 2) + i;
                __nv_bfloat16 hi = __float2bfloat16(vv[i]);
                __nv_bfloat16 lo = __float2bfloat16(vv[i] - __bfloat162float(hi));
                Vthi[d * VSTR + j] = hi;
                Vtlo[d * VSTR + j] = lo;
            }
        }
        __syncthreads();

        bool diag = (kt == qt);
        float li0 = Ls[wr + g], li1 = Ls[wr + 8 + g];

#pragma unroll
        for (int n = 0; n < 8; n++)
#pragma unroll
            for (int i = 0; i < 4; i++) acc_o[n][i] = 0.f;

#pragma unroll
        for (int kk = 0; kk < 8; kk++) {
            float uE[4], uO[4];
#pragma unroll
            for (int half = 0; half < 2; half++) {
                float* u = half ? uO : uE;
                int n = (kk << 1) + half;
                int cg = k0 + (n << 3) + (q << 1);
                u[0] = (diag && cg > gi0) ? 0.f : __expf(acc[n][0]);
                u[1] = (diag && cg + 1 > gi0) ? 0.f : __expf(acc[n][1]);
                u[2] = (diag && cg > gi1) ? 0.f : __expf(acc[n][2]);
                u[3] = (diag && cg + 1 > gi1) ? 0.f : __expf(acc[n][3]);
                __stcs((float2*)(Wh + (size_t)gi0 * S + cg),
                       make_float2(u[0] * li0, u[1] * li0));
                __stcs((float2*)(Wh + (size_t)gi1 * S + cg),
                       make_float2(u[2] * li1, u[3] * li1));
            }
            uint32_t ah[4], al[4];
            ah[0] = pk2(uE[0], uE[1]); ah[1] = pk2(uE[2], uE[3]);
            ah[2] = pk2(uO[0], uO[1]); ah[3] = pk2(uO[2], uO[3]);
            al[0] = pk2(uE[0] - __bfloat162float(__float2bfloat16(uE[0])),
                        uE[1] - __bfloat162float(__float2bfloat16(uE[1])));
            al[1] = pk2(uE[2] - __bfloat162float(__float2bfloat16(uE[2])),
                        uE[3] - __bfloat162float(__float2bfloat16(uE[3])));
            al[2] = pk2(uO[0] - __bfloat162float(__float2bfloat16(uO[0])),
                        uO[1] - __bfloat162float(__float2bfloat16(uO[1])));
            al[3] = pk2(uO[2] - __bfloat162float(__float2bfloat16(uO[2])),
                        uO[3] - __bfloat162float(__float2bfloat16(uO[3])));

#pragma unroll
            for (int dn2 = 0; dn2 < 4; dn2++) {
                uint32_t boff = (uint32_t)((((dn2 << 4) + ((L >> 4) << 3) + (L & 7)) * VSTR +
                                            (kk << 4) + (((L >> 3) & 1) << 3)) << 1);
                uint32_t bh[4], bl[4];
                ldsm4(bh, vhiB + boff);
                ldsm4(bl, vloB + boff);
                mma_bf16(acc_o[2 * dn2],     ah, &bh[0]);
                mma_bf16(acc_o[2 * dn2],     ah, &bl[0]);
                mma_bf16(acc_o[2 * dn2],     al, &bh[0]);
                mma_bf16(acc_o[2 * dn2 + 1], ah, &bh[2]);
                mma_bf16(acc_o[2 * dn2 + 1], ah, &bl[2]);
                mma_bf16(acc_o[2 * dn2 + 1], al, &bh[2]);
            }
        }

        if (two) {
            if (sub == 0) {
#pragma unroll
                for (int dn = 0; dn < 8; dn++) {
                    int c = (dn << 3) + (q << 1);
                    Osm[wr + g][c]     = acc_o[dn][0];
                    Osm[wr + g][c + 1] = acc_o[dn][1];
                    Osm[wr + 8 + g][c]     = acc_o[dn][2];
                    Osm[wr + 8 + g][c + 1] = acc_o[dn][3];
                }
            } else {
#pragma unroll
                for (int dn = 0; dn < 8; dn++) {
                    int c = (dn << 3) + (q << 1);
                    acc_o[dn][0] += Osm[wr + g][c];
                    acc_o[dn][1] += Osm[wr + g][c + 1];
                    acc_o[dn][2] += Osm[wr + 8 + g][c];
                    acc_o[dn][3] += Osm[wr + 8 + g][c + 1];
                }
            }
        }
    }

    float* P = g_part + (((size_t)(h * 16 + qt) << 3) + p) * (128 * 64);
#pragma unroll
    for (int dn = 0; dn < 8; dn++) {
        int c = (dn << 3) + (q << 1);
        __stcs((float2*)(P + (wr + g) * 64 + c),
               make_float2(acc_o[dn][0], acc_o[dn][1]));
        __stcs((float2*)(P + (wr + 8 + g) * 64 + c),
               make_float2(acc_o[dn][2], acc_o[dn][3]));
    }

    if (!two && kt0 + 1 <= 15) {
        float4 z = make_float4(0.f, 0.f, 0.f, 0.f);
        int c0 = (kt0 + 1) << 7;
        for (int e = t; e < 128 * 32; e += 256) {
            int r = e >> 5, c4 = e & 31;
            __stcs((float4*)(Wh + (size_t)(q0 + r) * S + c0 + (c4 << 2)), z);
        }
    }
}

// ---------------------------------------------------------------------------
// K3: reduce partials over k-pairs, scale by Linv, write O.
// ---------------------------------------------------------------------------
__global__ __launch_bounds__(256)
void pv_reduce(float* __restrict__ O) {
    int qt = blockIdx.x, h = blockIdx.y;
    int q0 = qt << 7;
    float* Oh = O + (size_t)h * S * D;
    __shared__ float Ls[128];
    int t = threadIdx.x;
    if (t < 128) {
        float Lsum = 0.f;
        for (int k2 = 0; k2 <= qt; k2++)
            Lsum += g_stats[(size_t)(h * 16 + k2) * S + q0 + t];
        Ls[t] = 1.f / Lsum;
    }
    __syncthreads();

    const float* Pb = g_part + ((size_t)(h * 16 + qt) << 3) * (128 * 64);
    int np = (qt >> 1) + 1;
    for (int f = t; f < 2048; f += 256) {
        float4 s = make_float4(0.f, 0.f, 0.f, 0.f);
        for (int p = 0; p < np; p++) {
            float4 v = __ldcs((const float4*)(Pb + (size_t)p * (128 * 64) + (f << 2)));
            s.x += v.x; s.y += v.y; s.z += v.z; s.w += v.w;
        }
        float li = Ls[f >> 4];
        *(float4*)(Oh + (size_t)q0 * D + (f << 2)) =
            make_float4(s.x * li, s.y * li, s.z * li, s.w * li);
    }
}

// ---------------------------------------------------------------------------
// fallback (output-only branch)
// ---------------------------------------------------------------------------
__global__ void fallback_kernel(const float* __restrict__ Q,
                                const float* __restrict__ K,
                                const float* __restrict__ V,
                                float* __restrict__ O) {
    int i = blockIdx.x, h = blockIdx.y;
    const float* Qh = Q + (size_t)h * S * D;
    const float* Kh = K + (size_t)h * S * D;
    const float* Vh = V + (size_t)h * S * D;
    float* Oh = O + (size_t)h * S * D;
    __shared__ float p[S];
    __shared__ float qsh[D];
    __shared__ float red[64];
    int t = threadIdx.x;
    qsh[t] = Qh[(size_t)i * D + t];
    __syncthreads();
    float lsum = 0.f;
    for (int j = t; j <= i; j += 64) {
        const float* kr = Kh + (size_t)j * D;
        float s = 0.f;
#pragma unroll 16
        for (int d = 0; d < D; d++) s = fmaf(qsh[d], kr[d], s);
        float e = __expf(s * SCALE);
        p[j] = e; lsum += e;
    }
    red[t] = lsum; __syncthreads();
    for (int s2 = 32; s2 > 0; s2 >>= 1) { if (t < s2) red[t] += red[t + s2]; __syncthreads(); }
    float inv = 1.0f / red[0];
    __syncthreads();
    float o = 0.f;
    for (int j = 0; j <= i; j++) o = fmaf(p[j], Vh[(size_t)j * D + t], o);
    Oh[(size_t)i * D + t] = o * inv;
}

// ---------------------------------------------------------------------------
extern "C" void kernel_launch(void* const* d_in, const int* in_sizes, int n_in,
                              void* d_out, int out_size) {
    const float* Q = (const float*)d_in[0];
    const float* K = (const float*)d_in[1];
    const float* V = (const float*)d_in[2];
    float* out = (float*)d_out;

    const long long O_ELEMS = (long long)NH * S * D;
    const long long W_ELEMS = (long long)NH * S * S;

    const int SMEM_TILES = 4 * 128 * STR * 2;   // 73728 B
    cudaFuncSetAttribute(stats_mma, cudaFuncAttributeMaxDynamicSharedMemorySize, SMEM_TILES);
    cudaFuncSetAttribute(emit_mma,  cudaFuncAttributeMaxDynamicSharedMemorySize, SMEM_TILES);

    if ((long long)out_size >= O_ELEMS + W_ELEMS) {
        float* W = out + O_ELEMS;
        stats_mma<<<dim3(8, 16, 32), 256, SMEM_TILES>>>(Q, K);
        emit_mma<<<dim3(8, 16, 32), 256, SMEM_TILES>>>(Q, K, V, W);
        pv_reduce<<<dim3(16, NH), 256>>>(out);
    } else if ((long long)out_size == W_ELEMS) {
        float* W = out;
        stats_mma<<<dim3(8, 16, 32), 256, SMEM_TILES>>>(Q, K);
        emit_mma<<<dim3(8, 16, 32), 256, SMEM_TILES>>>(Q, K, V, W);
    } else {
        fallback_kernel<<<dim3(S, NH), 64>>>(Q, K, V, out);
    }
}

// round 11
// speedup vs baseline: 1.0377x; 1.0377x over previous
#include <cuda_runtime.h>
#include <cuda_bf16.h>
#include <math.h>
#include <stdint.h>

#define S 2048
#define D 64
#define NH 32
#define SCALE 0.125f
#define STR 72            // Q/K smem row stride in bf16 (64 data + 8 pad)
#define VSTR 136          // Vt smem row stride in bf16 (128 data + 8 pad)

// per-(head, 128-wide k-tile, row) partial sums of exp(s)
__device__ float g_stats[(size_t)NH * 16 * S];
// split-K partial O over 256-wide k-pairs: [h][qt][p<8][128*64]
__device__ float g_part[(size_t)NH * 16 * 8 * 128 * 64];

// ------------------------------ helpers -----------------------------------
__device__ __forceinline__ uint32_t smem_u32(const void* p) {
    return (uint32_t)__cvta_generic_to_shared(p);
}
__device__ __forceinline__ void ldsm4(uint32_t* r, uint32_t addr) {
    asm volatile("ldmatrix.sync.aligned.m8n8.x4.shared.b16 {%0,%1,%2,%3}, [%4];"
                 : "=r"(r[0]), "=r"(r[1]), "=r"(r[2]), "=r"(r[3]) : "r"(addr));
}
__device__ __forceinline__ void ldsm2(uint32_t* r, uint32_t addr) {
    asm volatile("ldmatrix.sync.aligned.m8n8.x2.shared.b16 {%0,%1}, [%2];"
                 : "=r"(r[0]), "=r"(r[1]) : "r"(addr));
}
__device__ __forceinline__ void mma_bf16(float* c, const uint32_t* a, const uint32_t* b) {
    asm volatile("mma.sync.aligned.m16n8k16.row.col.f32.bf16.bf16.f32 "
                 "{%0,%1,%2,%3},{%4,%5,%6,%7},{%8,%9},{%0,%1,%2,%3};"
                 : "+f"(c[0]), "+f"(c[1]), "+f"(c[2]), "+f"(c[3])
                 : "r"(a[0]), "r"(a[1]), "r"(a[2]), "r"(a[3]), "r"(b[0]), "r"(b[1]));
}
__device__ __forceinline__ void split4(__nv_bfloat16* hi, __nv_bfloat16* lo,
                                       int off, float4 v) {
    __nv_bfloat16 h0 = __float2bfloat16(v.x), h1 = __float2bfloat16(v.y);
    __nv_bfloat16 h2 = __float2bfloat16(v.z), h3 = __float2bfloat16(v.w);
    __nv_bfloat16 l0 = __float2bfloat16(v.x - __bfloat162float(h0));
    __nv_bfloat16 l1 = __float2bfloat16(v.y - __bfloat162float(h1));
    __nv_bfloat16 l2 = __float2bfloat16(v.z - __bfloat162float(h2));
    __nv_bfloat16 l3 = __float2bfloat16(v.w - __bfloat162float(h3));
    uint2 hv = make_uint2((uint32_t)__bfloat16_as_ushort(h0) | ((uint32_t)__bfloat16_as_ushort(h1) << 16),
                          (uint32_t)__bfloat16_as_ushort(h2) | ((uint32_t)__bfloat16_as_ushort(h3) << 16));
    uint2 lv = make_uint2((uint32_t)__bfloat16_as_ushort(l0) | ((uint32_t)__bfloat16_as_ushort(l1) << 16),
                          (uint32_t)__bfloat16_as_ushort(l2) | ((uint32_t)__bfloat16_as_ushort(l3) << 16));
    *(uint2*)(hi + off) = hv;
    *(uint2*)(lo + off) = lv;
}
__device__ __forceinline__ uint32_t pk2(float a, float b) {
    __nv_bfloat162 h = __floats2bfloat162_rn(a, b);
    return *(uint32_t*)&h;
}

__device__ __forceinline__ void stage_q(const float* Qh, int q0, int t,
                                        __nv_bfloat16* Qhi, __nv_bfloat16* Qlo) {
    for (int e = t; e < 128 * 16; e += 256) {
        int r = e >> 4, c4 = e & 15;
        float4 q4 = *(const float4*)(Qh + (size_t)(q0 + r) * D + (c4 << 2));
        q4.x *= SCALE; q4.y *= SCALE; q4.z *= SCALE; q4.w *= SCALE;
        split4(Qhi, Qlo, r * STR + (c4 << 2), q4);
    }
}
__device__ __forceinline__ void stage_k(const float* Kh, int k0, int t,
                                        __nv_bfloat16* Khi, __nv_bfloat16* Klo) {
    for (int e = t; e < 128 * 16; e += 256) {
        int r = e >> 4, c4 = e & 15;
        float4 k4 = *(const float4*)(Kh + (size_t)(k0 + r) * D + (c4 << 2));
        split4(Khi, Klo, r * STR + (c4 << 2), k4);
    }
}

// full-precision QK^T (3 MMA), ldsm4-paired B (emit)
__device__ __forceinline__ void qk_mma8(uint32_t qhiB, uint32_t qloB,
                                        uint32_t khiB, uint32_t kloB,
                                        int wr, int L, float acc[16][4]) {
#pragma unroll
    for (int kk = 0; kk < 4; kk++) {
        uint32_t ah[4], al[4];
        uint32_t aoff = (uint32_t)(((wr + (L & 15)) * STR + (kk << 4) + ((L >> 4) << 3)) << 1);
        ldsm4(ah, qhiB + aoff);
        ldsm4(al, qloB + aoff);
#pragma unroll
        for (int n2 = 0; n2 < 8; n2++) {
            uint32_t boff = (uint32_t)((((n2 << 4) + ((L >> 4) << 3) + (L & 7)) * STR +
                                        (kk << 4) + (((L >> 3) & 1) << 3)) << 1);
            uint32_t bh[4], bl[4];
            ldsm4(bh, khiB + boff);
            ldsm4(bl, kloB + boff);
            mma_bf16(acc[2 * n2],     ah, &bh[0]);
            mma_bf16(acc[2 * n2],     ah, &bl[0]);
            mma_bf16(acc[2 * n2],     al, &bh[0]);
            mma_bf16(acc[2 * n2 + 1], ah, &bh[2]);
            mma_bf16(acc[2 * n2 + 1], ah, &bl[2]);
            mma_bf16(acc[2 * n2 + 1], al, &bh[2]);
        }
    }
}

// ---------------------------------------------------------------------------
// K1: stats — full-precision QK per 256-wide k-pair, rowsums -> g_stats.
// Masked-band CTAs zero-fill W instead of idling (overlaps idle DRAM).
// Register-lean n-outer loop -> 3 CTAs/SM.
// ---------------------------------------------------------------------------
__global__ __launch_bounds__(256, 3)
void stats_mma(const float* __restrict__ Q, const float* __restrict__ Km,
               float* __restrict__ W) {
    int p = blockIdx.x, qt = 15 - blockIdx.y, h = blockIdx.z;
    int kt0 = p << 1;
    int q0 = qt << 7;
    int t = threadIdx.x;
    float* Wh = W + (size_t)h * S * S;

    if (kt0 > qt) {                      // masked band: final W is 0
        float4 z = make_float4(0.f, 0.f, 0.f, 0.f);
        int c0 = kt0 << 7;
        for (int e = t; e < 128 * 64; e += 256) {
            int r = e >> 6, c4 = e & 63;
            __stcs((float4*)(Wh + (size_t)(q0 + r) * S + c0 + (c4 << 2)), z);
        }
        return;
    }

    extern __shared__ char smraw[];
    __nv_bfloat16* Qhi = (__nv_bfloat16*)smraw;
    __nv_bfloat16* Qlo = Qhi + 128 * STR;
    __nv_bfloat16* Khi = Qlo + 128 * STR;
    __nv_bfloat16* Klo = Khi + 128 * STR;

    stage_q(Q + (size_t)h * S * D, q0, t, Qhi, Qlo);

    const float* Kh = Km + (size_t)h * S * D;
    int w = t >> 5, L = t & 31;
    int wr = w << 4;
    int g = L >> 2, q = L & 3;
    int gi0 = q0 + wr + g, gi1 = gi0 + 8;
    uint32_t qhiB = smem_u32(Qhi), qloB = smem_u32(Qlo);
    uint32_t khiB = smem_u32(Khi), kloB = smem_u32(Klo);

#pragma unroll 1
    for (int sub = 0; sub < 2; sub++) {
        int kt = kt0 + sub;
        if (kt > qt) break;
        int k0 = kt << 7;
        __syncthreads();
        stage_k(Kh, k0, t, Khi, Klo);
        __syncthreads();

        // preload all A fragments (held across the n loop)
        uint32_t ah[4][4], al[4][4];
#pragma unroll
        for (int kk = 0; kk < 4; kk++) {
            uint32_t aoff = (uint32_t)(((wr + (L & 15)) * STR + (kk << 4) + ((L >> 4) << 3)) << 1);
            ldsm4(ah[kk], qhiB + aoff);
            ldsm4(al[kk], qloB + aoff);
        }

        float s0 = 0.f, s1 = 0.f;
        bool diag = (kt == qt);
#pragma unroll
        for (int n = 0; n < 16; n++) {
            float acc[4] = {0.f, 0.f, 0.f, 0.f};
#pragma unroll
            for (int kk = 0; kk < 4; kk++) {
                uint32_t boff = (uint32_t)((((n << 3) + (L & 7)) * STR +
                                            (kk << 4) + (((L >> 3) & 1) << 3)) << 1);
                uint32_t bh[2], bl[2];
                ldsm2(bh, khiB + boff);
                ldsm2(bl, kloB + boff);
                mma_bf16(acc, ah[kk], bh);
                mma_bf16(acc, ah[kk], bl);
                mma_bf16(acc, al[kk], bh);
            }
            if (diag) {
                int cg = k0 + (n << 3) + (q << 1);
                s0 += ((cg > gi0) ? 0.f : __expf(acc[0])) +
                      ((cg + 1 > gi0) ? 0.f : __expf(acc[1]));
                s1 += ((cg > gi1) ? 0.f : __expf(acc[2])) +
                      ((cg + 1 > gi1) ? 0.f : __expf(acc[3]));
            } else {
                s0 += __expf(acc[0]) + __expf(acc[1]);
                s1 += __expf(acc[2]) + __expf(acc[3]);
            }
        }
        s0 += __shfl_xor_sync(0xffffffffu, s0, 1);
        s0 += __shfl_xor_sync(0xffffffffu, s0, 2);
        s1 += __shfl_xor_sync(0xffffffffu, s1, 1);
        s1 += __shfl_xor_sync(0xffffffffu, s1, 2);
        if (q == 0) {
            size_t sb = (size_t)(h * 16 + kt) * S;
            g_stats[sb + gi0] = s0;
            g_stats[sb + gi1] = s1;
        }
    }

    // odd-straddle: qt even & kt0 == qt -> tile kt0+1 is fully masked
    if (kt0 == qt && kt0 + 1 <= 15) {
        float4 z = make_float4(0.f, 0.f, 0.f, 0.f);
        int c0 = (kt0 + 1) << 7;
        for (int e = t; e < 128 * 32; e += 256) {
            int r = e >> 5, c4 = e & 31;
            __stcs((float4*)(Wh + (size_t)(q0 + r) * S + c0 + (c4 << 2)), z);
        }
    }
}

// ---------------------------------------------------------------------------
// K2: emit — per (h, qt, 256-wide k-pair): recompute s (full precision),
// write final W = exp(s)*Linv once, fused PV; pair-partial O -> g_part.
// Zero-fill is handled by stats_mma now.
// ---------------------------------------------------------------------------
__global__ __launch_bounds__(256, 2)
void emit_mma(const float* __restrict__ Q, const float* __restrict__ Km,
              const float* __restrict__ V, float* __restrict__ W) {
    int p = blockIdx.x, qt = 15 - blockIdx.y, h = blockIdx.z;
    int kt0 = p << 1;
    if (kt0 > qt) return;                // zero-fill done in stats_mma
    float* Wh = W + (size_t)h * S * S;
    int q0 = qt << 7;
    int t = threadIdx.x;

    extern __shared__ char smraw[];
    __nv_bfloat16* Qhi = (__nv_bfloat16*)smraw;
    __nv_bfloat16* Qlo = Qhi + 128 * STR;
    __nv_bfloat16* Khi = Qlo + 128 * STR;
    __nv_bfloat16* Klo = Khi + 128 * STR;
    __nv_bfloat16* Vthi = Khi;           // reused after QK mma
    __nv_bfloat16* Vtlo = Klo;
    __shared__ float Ls[128];
    __shared__ float Osm[128][68];

    const float* Vh = V + (size_t)h * S * D;

    if (t < 128) {
        float Lsum = 0.f;
        for (int k2 = 0; k2 <= qt; k2++)
            Lsum += g_stats[(size_t)(h * 16 + k2) * S + q0 + t];
        Ls[t] = 1.f / Lsum;
    }
    stage_q(Q + (size_t)h * S * D, q0, t, Qhi, Qlo);

    int w = t >> 5, L = t & 31;
    int wr = w << 4;
    int g = L >> 2, q = L & 3;
    int gi0 = q0 + wr + g, gi1 = gi0 + 8;
    uint32_t vhiB = smem_u32(Vthi), vloB = smem_u32(Vtlo);
    bool two = (kt0 + 1 <= qt);

    float acc_o[8][4];

#pragma unroll 1
    for (int sub = 0; sub < 2; sub++) {
        int kt = kt0 + sub;
        if (kt > qt) break;
        int k0 = kt << 7;
        __syncthreads();
        stage_k(Km + (size_t)h * S * D, k0, t, Khi, Klo);
        __syncthreads();

        float acc[16][4];
#pragma unroll
        for (int n = 0; n < 16; n++)
#pragma unroll
            for (int i = 0; i < 4; i++) acc[n][i] = 0.f;
        qk_mma8(smem_u32(Qhi), smem_u32(Qlo), smem_u32(Khi), smem_u32(Klo), wr, L, acc);
        __syncthreads();

        for (int e = t; e < 128 * 16; e += 256) {
            int j = e >> 4, d4 = e & 15;
            float4 v4 = *(const float4*)(Vh + (size_t)(k0 + j) * D + (d4 << 2));
            float vv[4] = {v4.x, v4.y, v4.z, v4.w};
#pragma unroll
            for (int i = 0; i < 4; i++) {
                int d = (d4 << 2) + i;
                __nv_bfloat16 hi = __float2bfloat16(vv[i]);
                __nv_bfloat16 lo = __float2bfloat16(vv[i] - __bfloat162float(hi));
                Vthi[d * VSTR + j] = hi;
                Vtlo[d * VSTR + j] = lo;
            }
        }
        __syncthreads();

        bool diag = (kt == qt);
        float li0 = Ls[wr + g], li1 = Ls[wr + 8 + g];

#pragma unroll
        for (int n = 0; n < 8; n++)
#pragma unroll
            for (int i = 0; i < 4; i++) acc_o[n][i] = 0.f;

#pragma unroll
        for (int kk = 0; kk < 8; kk++) {
            float uE[4], uO[4];
#pragma unroll
            for (int half = 0; half < 2; half++) {
                float* u = half ? uO : uE;
                int n = (kk << 1) + half;
                int cg = k0 + (n << 3) + (q << 1);
                u[0] = (diag && cg > gi0) ? 0.f : __expf(acc[n][0]);
                u[1] = (diag && cg + 1 > gi0) ? 0.f : __expf(acc[n][1]);
                u[2] = (diag && cg > gi1) ? 0.f : __expf(acc[n][2]);
                u[3] = (diag && cg + 1 > gi1) ? 0.f : __expf(acc[n][3]);
                __stcs((float2*)(Wh + (size_t)gi0 * S + cg),
                       make_float2(u[0] * li0, u[1] * li0));
                __stcs((float2*)(Wh + (size_t)gi1 * S + cg),
                       make_float2(u[2] * li1, u[3] * li1));
            }
            uint32_t ah[4], al[4];
            ah[0] = pk2(uE[0], uE[1]); ah[1] = pk2(uE[2], uE[3]);
            ah[2] = pk2(uO[0], uO[1]); ah[3] = pk2(uO[2], uO[3]);
            al[0] = pk2(uE[0] - __bfloat162float(__float2bfloat16(uE[0])),
                        uE[1] - __bfloat162float(__float2bfloat16(uE[1])));
            al[1] = pk2(uE[2] - __bfloat162float(__float2bfloat16(uE[2])),
                        uE[3] - __bfloat162float(__float2bfloat16(uE[3])));
            al[2] = pk2(uO[0] - __bfloat162float(__float2bfloat16(uO[0])),
                        uO[1] - __bfloat162float(__float2bfloat16(uO[1])));
            al[3] = pk2(uO[2] - __bfloat162float(__float2bfloat16(uO[2])),
                        uO[3] - __bfloat162float(__float2bfloat16(uO[3])));

#pragma unroll
            for (int dn2 = 0; dn2 < 4; dn2++) {
                uint32_t boff = (uint32_t)((((dn2 << 4) + ((L >> 4) << 3) + (L & 7)) * VSTR +
                                            (kk << 4) + (((L >> 3) & 1) << 3)) << 1);
                uint32_t bh[4], bl[4];
                ldsm4(bh, vhiB + boff);
                ldsm4(bl, vloB + boff);
                mma_bf16(acc_o[2 * dn2],     ah, &bh[0]);
                mma_bf16(acc_o[2 * dn2],     ah, &bl[0]);
                mma_bf16(acc_o[2 * dn2],     al, &bh[0]);
                mma_bf16(acc_o[2 * dn2 + 1], ah, &bh[2]);
                mma_bf16(acc_o[2 * dn2 + 1], ah, &bl[2]);
                mma_bf16(acc_o[2 * dn2 + 1], al, &bh[2]);
            }
        }

        if (two) {
            if (sub == 0) {
#pragma unroll
                for (int dn = 0; dn < 8; dn++) {
                    int c = (dn << 3) + (q << 1);
                    Osm[wr + g][c]     = acc_o[dn][0];
                    Osm[wr + g][c + 1] = acc_o[dn][1];
                    Osm[wr + 8 + g][c]     = acc_o[dn][2];
                    Osm[wr + 8 + g][c + 1] = acc_o[dn][3];
                }
            } else {
#pragma unroll
                for (int dn = 0; dn < 8; dn++) {
                    int c = (dn << 3) + (q << 1);
                    acc_o[dn][0] += Osm[wr + g][c];
                    acc_o[dn][1] += Osm[wr + g][c + 1];
                    acc_o[dn][2] += Osm[wr + 8 + g][c];
                    acc_o[dn][3] += Osm[wr + 8 + g][c + 1];
                }
            }
        }
    }

    float* P = g_part + (((size_t)(h * 16 + qt) << 3) + p) * (128 * 64);
#pragma unroll
    for (int dn = 0; dn < 8; dn++) {
        int c = (dn << 3) + (q << 1);
        __stcs((float2*)(P + (wr + g) * 64 + c),
               make_float2(acc_o[dn][0], acc_o[dn][1]));
        __stcs((float2*)(P + (wr + 8 + g) * 64 + c),
               make_float2(acc_o[dn][2], acc_o[dn][3]));
    }
}

// ---------------------------------------------------------------------------
// K3: reduce partials over k-pairs, scale by Linv, write O.
// ---------------------------------------------------------------------------
__global__ __launch_bounds__(256)
void pv_reduce(float* __restrict__ O) {
    int qt = blockIdx.x, h = blockIdx.y;
    int q0 = qt << 7;
    float* Oh = O + (size_t)h * S * D;
    __shared__ float Ls[128];
    int t = threadIdx.x;
    if (t < 128) {
        float Lsum = 0.f;
        for (int k2 = 0; k2 <= qt; k2++)
            Lsum += g_stats[(size_t)(h * 16 + k2) * S + q0 + t];
        Ls[t] = 1.f / Lsum;
    }
    __syncthreads();

    const float* Pb = g_part + ((size_t)(h * 16 + qt) << 3) * (128 * 64);
    int np = (qt >> 1) + 1;
    for (int f = t; f < 2048; f += 256) {
        float4 s = make_float4(0.f, 0.f, 0.f, 0.f);
        for (int p = 0; p < np; p++) {
            float4 v = __ldcs((const float4*)(Pb + (size_t)p * (128 * 64) + (f << 2)));
            s.x += v.x; s.y += v.y; s.z += v.z; s.w += v.w;
        }
        float li = Ls[f >> 4];
        *(float4*)(Oh + (size_t)q0 * D + (f << 2)) =
            make_float4(s.x * li, s.y * li, s.z * li, s.w * li);
    }
}

// ---------------------------------------------------------------------------
// fallback (output-only branch)
// ---------------------------------------------------------------------------
__global__ void fallback_kernel(const float* __restrict__ Q,
                                const float* __restrict__ K,
                                const float* __restrict__ V,
                                float* __restrict__ O) {
    int i = blockIdx.x, h = blockIdx.y;
    const float* Qh = Q + (size_t)h * S * D;
    const float* Kh = K + (size_t)h * S * D;
    const float* Vh = V + (size_t)h * S * D;
    float* Oh = O + (size_t)h * S * D;
    __shared__ float p[S];
    __shared__ float qsh[D];
    __shared__ float red[64];
    int t = threadIdx.x;
    qsh[t] = Qh[(size_t)i * D + t];
    __syncthreads();
    float lsum = 0.f;
    for (int j = t; j <= i; j += 64) {
        const float* kr = Kh + (size_t)j * D;
        float s = 0.f;
#pragma unroll 16
        for (int d = 0; d < D; d++) s = fmaf(qsh[d], kr[d], s);
        float e = __expf(s * SCALE);
        p[j] = e; lsum += e;
    }
    red[t] = lsum; __syncthreads();
    for (int s2 = 32; s2 > 0; s2 >>= 1) { if (t < s2) red[t] += red[t + s2]; __syncthreads(); }
    float inv = 1.0f / red[0];
    __syncthreads();
    float o = 0.f;
    for (int j = 0; j <= i; j++) o = fmaf(p[j], Vh[(size_t)j * D + t], o);
    Oh[(size_t)i * D + t] = o * inv;
}

// ---------------------------------------------------------------------------
extern "C" void kernel_launch(void* const* d_in, const int* in_sizes, int n_in,
                              void* d_out, int out_size) {
    const float* Q = (const float*)d_in[0];
    const float* K = (const float*)d_in[1];
    const float* V = (const float*)d_in[2];
    float* out = (float*)d_out;

    const long long O_ELEMS = (long long)NH * S * D;
    const long long W_ELEMS = (long long)NH * S * S;

    const int SMEM_TILES = 4 * 128 * STR * 2;   // 73728 B
    cudaFuncSetAttribute(stats_mma, cudaFuncAttributeMaxDynamicSharedMemorySize, SMEM_TILES);
    cudaFuncSetAttribute(emit_mma,  cudaFuncAttributeMaxDynamicSharedMemorySize, SMEM_TILES);

    if ((long long)out_size >= O_ELEMS + W_ELEMS) {
        float* W = out + O_ELEMS;
        stats_mma<<<dim3(8, 16, 32), 256, SMEM_TILES>>>(Q, K, W);
        emit_mma<<<dim3(8, 16, 32), 256, SMEM_TILES>>>(Q, K, V, W);
        pv_reduce<<<dim3(16, NH), 256>>>(out);
    } else if ((long long)out_size == W_ELEMS) {
        float* W = out;
        stats_mma<<<dim3(8, 16, 32), 256, SMEM_TILES>>>(Q, K, W);
        emit_mma<<<dim3(8, 16, 32), 256, SMEM_TILES>>>(Q, K, V, W);
    } else {
        fallback_kernel<<<dim3(S, NH), 64>>>(Q, K, V, out);
    }
}

// round 12
// speedup vs baseline: 1.0577x; 1.0193x over previous
#include <cuda_runtime.h>
#include <cuda_bf16.h>
#include <math.h>
#include <stdint.h>

#define S 2048
#define D 64
#define NH 32
#define SCALE 0.125f
#define STR 72            // Q/K smem row stride in bf16 (64 data + 8 pad)
#define VSTR 136          // Vt smem row stride in bf16 (128 data + 8 pad)

// per-(head, 128-wide k-tile, row) partial sums of exp(s)
__device__ float g_stats[(size_t)NH * 16 * S];
// split-K partial O over 512-wide k-quads: [h][qt][p<4][128*64]
__device__ float g_part[(size_t)NH * 16 * 4 * 128 * 64];
// completion counters per (h, qt)
__device__ int g_cnt[NH * 16];
// scratch O for the weights-only branch
__device__ float g_Oscratch[(size_t)NH * S * D];

// ------------------------------ helpers -----------------------------------
__device__ __forceinline__ uint32_t smem_u32(const void* p) {
    return (uint32_t)__cvta_generic_to_shared(p);
}
__device__ __forceinline__ void ldsm4(uint32_t* r, uint32_t addr) {
    asm volatile("ldmatrix.sync.aligned.m8n8.x4.shared.b16 {%0,%1,%2,%3}, [%4];"
                 : "=r"(r[0]), "=r"(r[1]), "=r"(r[2]), "=r"(r[3]) : "r"(addr));
}
__device__ __forceinline__ void ldsm2(uint32_t* r, uint32_t addr) {
    asm volatile("ldmatrix.sync.aligned.m8n8.x2.shared.b16 {%0,%1}, [%2];"
                 : "=r"(r[0]), "=r"(r[1]) : "r"(addr));
}
__device__ __forceinline__ void mma_bf16(float* c, const uint32_t* a, const uint32_t* b) {
    asm volatile("mma.sync.aligned.m16n8k16.row.col.f32.bf16.bf16.f32 "
                 "{%0,%1,%2,%3},{%4,%5,%6,%7},{%8,%9},{%0,%1,%2,%3};"
                 : "+f"(c[0]), "+f"(c[1]), "+f"(c[2]), "+f"(c[3])
                 : "r"(a[0]), "r"(a[1]), "r"(a[2]), "r"(a[3]), "r"(b[0]), "r"(b[1]));
}
__device__ __forceinline__ void split4(__nv_bfloat16* hi, __nv_bfloat16* lo,
                                       int off, float4 v) {
    __nv_bfloat16 h0 = __float2bfloat16(v.x), h1 = __float2bfloat16(v.y);
    __nv_bfloat16 h2 = __float2bfloat16(v.z), h3 = __float2bfloat16(v.w);
    __nv_bfloat16 l0 = __float2bfloat16(v.x - __bfloat162float(h0));
    __nv_bfloat16 l1 = __float2bfloat16(v.y - __bfloat162float(h1));
    __nv_bfloat16 l2 = __float2bfloat16(v.z - __bfloat162float(h2));
    __nv_bfloat16 l3 = __float2bfloat16(v.w - __bfloat162float(h3));
    uint2 hv = make_uint2((uint32_t)__bfloat16_as_ushort(h0) | ((uint32_t)__bfloat16_as_ushort(h1) << 16),
                          (uint32_t)__bfloat16_as_ushort(h2) | ((uint32_t)__bfloat16_as_ushort(h3) << 16));
    uint2 lv = make_uint2((uint32_t)__bfloat16_as_ushort(l0) | ((uint32_t)__bfloat16_as_ushort(l1) << 16),
                          (uint32_t)__bfloat16_as_ushort(l2) | ((uint32_t)__bfloat16_as_ushort(l3) << 16));
    *(uint2*)(hi + off) = hv;
    *(uint2*)(lo + off) = lv;
}
__device__ __forceinline__ uint32_t pk2(float a, float b) {
    __nv_bfloat162 h = __floats2bfloat162_rn(a, b);
    return *(uint32_t*)&h;
}

__device__ __forceinline__ void stage_q(const float* Qh, int q0, int t,
                                        __nv_bfloat16* Qhi, __nv_bfloat16* Qlo) {
    for (int e = t; e < 128 * 16; e += 256) {
        int r = e >> 4, c4 = e & 15;
        float4 q4 = *(const float4*)(Qh + (size_t)(q0 + r) * D + (c4 << 2));
        q4.x *= SCALE; q4.y *= SCALE; q4.z *= SCALE; q4.w *= SCALE;
        split4(Qhi, Qlo, r * STR + (c4 << 2), q4);
    }
}
__device__ __forceinline__ void stage_k(const float* Kh, int k0, int t,
                                        __nv_bfloat16* Khi, __nv_bfloat16* Klo) {
    for (int e = t; e < 128 * 16; e += 256) {
        int r = e >> 4, c4 = e & 15;
        float4 k4 = *(const float4*)(Kh + (size_t)(k0 + r) * D + (c4 << 2));
        split4(Khi, Klo, r * STR + (c4 << 2), k4);
    }
}

// full-precision QK^T (3 MMA), ldsm4-paired B (emit)
__device__ __forceinline__ void qk_mma8(uint32_t qhiB, uint32_t qloB,
                                        uint32_t khiB, uint32_t kloB,
                                        int wr, int L, float acc[16][4]) {
#pragma unroll
    for (int kk = 0; kk < 4; kk++) {
        uint32_t ah[4], al[4];
        uint32_t aoff = (uint32_t)(((wr + (L & 15)) * STR + (kk << 4) + ((L >> 4) << 3)) << 1);
        ldsm4(ah, qhiB + aoff);
        ldsm4(al, qloB + aoff);
#pragma unroll
        for (int n2 = 0; n2 < 8; n2++) {
            uint32_t boff = (uint32_t)((((n2 << 4) + ((L >> 4) << 3) + (L & 7)) * STR +
                                        (kk << 4) + (((L >> 3) & 1) << 3)) << 1);
            uint32_t bh[4], bl[4];
            ldsm4(bh, khiB + boff);
            ldsm4(bl, kloB + boff);
            mma_bf16(acc[2 * n2],     ah, &bh[0]);
            mma_bf16(acc[2 * n2],     ah, &bl[0]);
            mma_bf16(acc[2 * n2],     al, &bh[0]);
            mma_bf16(acc[2 * n2 + 1], ah, &bh[2]);
            mma_bf16(acc[2 * n2 + 1], ah, &bl[2]);
            mma_bf16(acc[2 * n2 + 1], al, &bh[2]);
        }
    }
}

// ---------------------------------------------------------------------------
// K1: stats — full-precision QK per 256-wide k-pair, rowsums -> g_stats.
// Masked-band CTAs zero-fill W; p==0 CTAs also reset the emit counters.
// ---------------------------------------------------------------------------
__global__ __launch_bounds__(256, 3)
void stats_mma(const float* __restrict__ Q, const float* __restrict__ Km,
               float* __restrict__ W) {
    int p = blockIdx.x, qt = 15 - blockIdx.y, h = blockIdx.z;
    int kt0 = p << 1;
    int q0 = qt << 7;
    int t = threadIdx.x;
    float* Wh = W + (size_t)h * S * S;

    if (p == 0 && t == 0) g_cnt[(h << 4) + qt] = 0;   // reset emit counter

    if (kt0 > qt) {                      // masked band: final W is 0
        float4 z = make_float4(0.f, 0.f, 0.f, 0.f);
        int c0 = kt0 << 7;
        for (int e = t; e < 128 * 64; e += 256) {
            int r = e >> 6, c4 = e & 63;
            __stcs((float4*)(Wh + (size_t)(q0 + r) * S + c0 + (c4 << 2)), z);
        }
        return;
    }

    extern __shared__ char smraw[];
    __nv_bfloat16* Qhi = (__nv_bfloat16*)smraw;
    __nv_bfloat16* Qlo = Qhi + 128 * STR;
    __nv_bfloat16* Khi = Qlo + 128 * STR;
    __nv_bfloat16* Klo = Khi + 128 * STR;

    stage_q(Q + (size_t)h * S * D, q0, t, Qhi, Qlo);

    const float* Kh = Km + (size_t)h * S * D;
    int w = t >> 5, L = t & 31;
    int wr = w << 4;
    int g = L >> 2, q = L & 3;
    int gi0 = q0 + wr + g, gi1 = gi0 + 8;
    uint32_t qhiB = smem_u32(Qhi), qloB = smem_u32(Qlo);
    uint32_t khiB = smem_u32(Khi), kloB = smem_u32(Klo);

#pragma unroll 1
    for (int sub = 0; sub < 2; sub++) {
        int kt = kt0 + sub;
        if (kt > qt) break;
        int k0 = kt << 7;
        __syncthreads();
        stage_k(Kh, k0, t, Khi, Klo);
        __syncthreads();

        uint32_t ah[4][4], al[4][4];
#pragma unroll
        for (int kk = 0; kk < 4; kk++) {
            uint32_t aoff = (uint32_t)(((wr + (L & 15)) * STR + (kk << 4) + ((L >> 4) << 3)) << 1);
            ldsm4(ah[kk], qhiB + aoff);
            ldsm4(al[kk], qloB + aoff);
        }

        float s0 = 0.f, s1 = 0.f;
        bool diag = (kt == qt);
#pragma unroll
        for (int n = 0; n < 16; n++) {
            float acc[4] = {0.f, 0.f, 0.f, 0.f};
#pragma unroll
            for (int kk = 0; kk < 4; kk++) {
                uint32_t boff = (uint32_t)((((n << 3) + (L & 7)) * STR +
                                            (kk << 4) + (((L >> 3) & 1) << 3)) << 1);
                uint32_t bh[2], bl[2];
                ldsm2(bh, khiB + boff);
                ldsm2(bl, kloB + boff);
                mma_bf16(acc, ah[kk], bh);
                mma_bf16(acc, ah[kk], bl);
                mma_bf16(acc, al[kk], bh);
            }
            if (diag) {
                int cg = k0 + (n << 3) + (q << 1);
                s0 += ((cg > gi0) ? 0.f : __expf(acc[0])) +
                      ((cg + 1 > gi0) ? 0.f : __expf(acc[1]));
                s1 += ((cg > gi1) ? 0.f : __expf(acc[2])) +
                      ((cg + 1 > gi1) ? 0.f : __expf(acc[3]));
            } else {
                s0 += __expf(acc[0]) + __expf(acc[1]);
                s1 += __expf(acc[2]) + __expf(acc[3]);
            }
        }
        s0 += __shfl_xor_sync(0xffffffffu, s0, 1);
        s0 += __shfl_xor_sync(0xffffffffu, s0, 2);
        s1 += __shfl_xor_sync(0xffffffffu, s1, 1);
        s1 += __shfl_xor_sync(0xffffffffu, s1, 2);
        if (q == 0) {
            size_t sb = (size_t)(h * 16 + kt) * S;
            g_stats[sb + gi0] = s0;
            g_stats[sb + gi1] = s1;
        }
    }

    // odd-straddle: qt even & kt0 == qt -> tile kt0+1 is fully masked
    if (kt0 == qt && kt0 + 1 <= 15) {
        float4 z = make_float4(0.f, 0.f, 0.f, 0.f);
        int c0 = (kt0 + 1) << 7;
        for (int e = t; e < 128 * 32; e += 256) {
            int r = e >> 5, c4 = e & 31;
            __stcs((float4*)(Wh + (size_t)(q0 + r) * S + c0 + (c4 << 2)), z);
        }
    }
}

// ---------------------------------------------------------------------------
// K2: emit — per (h, qt, 512-wide k-quad): recompute s (full precision),
// write final W = exp(s)*Linv once, fused PV; quad-partial O -> g_part.
// Last CTA per (h, qt) reduces the partials (fixed order) and writes O.
// ---------------------------------------------------------------------------
__global__ __launch_bounds__(256, 2)
void emit_mma(const float* __restrict__ Q, const float* __restrict__ Km,
              const float* __restrict__ V, float* __restrict__ W,
              float* __restrict__ O) {
    int p = blockIdx.x, qt = 15 - blockIdx.y, h = blockIdx.z;
    int kt0 = p << 2;
    if (kt0 > qt) return;                // zero-fill done in stats_mma
    float* Wh = W + (size_t)h * S * S;
    int q0 = qt << 7;
    int t = threadIdx.x;

    extern __shared__ char smraw[];
    __nv_bfloat16* Qhi = (__nv_bfloat16*)smraw;
    __nv_bfloat16* Qlo = Qhi + 128 * STR;
    __nv_bfloat16* Khi = Qlo + 128 * STR;
    __nv_bfloat16* Klo = Khi + 128 * STR;
    __nv_bfloat16* Vthi = Khi;           // reused after QK mma
    __nv_bfloat16* Vtlo = Klo;
    __shared__ float Ls[128];
    __shared__ float Osm[128][68];
    __shared__ int isLast;

    const float* Vh = V + (size_t)h * S * D;

    if (t < 128) {
        float Lsum = 0.f;
        for (int k2 = 0; k2 <= qt; k2++)
            Lsum += g_stats[(size_t)(h * 16 + k2) * S + q0 + t];
        Ls[t] = 1.f / Lsum;
    }
    stage_q(Q + (size_t)h * S * D, q0, t, Qhi, Qlo);

    int w = t >> 5, L = t & 31;
    int wr = w << 4;
    int g = L >> 2, q = L & 3;
    int gi0 = q0 + wr + g, gi1 = gi0 + 8;
    uint32_t vhiB = smem_u32(Vthi), vloB = smem_u32(Vtlo);

#pragma unroll 1
    for (int sub = 0; sub < 4; sub++) {
        int kt = kt0 + sub;
        if (kt > qt) break;
        int k0 = kt << 7;
        __syncthreads();
        stage_k(Km + (size_t)h * S * D, k0, t, Khi, Klo);
        __syncthreads();

        float acc[16][4];
#pragma unroll
        for (int n = 0; n < 16; n++)
#pragma unroll
            for (int i = 0; i < 4; i++) acc[n][i] = 0.f;
        qk_mma8(smem_u32(Qhi), smem_u32(Qlo), smem_u32(Khi), smem_u32(Klo), wr, L, acc);
        __syncthreads();

        for (int e = t; e < 128 * 16; e += 256) {
            int j = e >> 4, d4 = e & 15;
            float4 v4 = *(const float4*)(Vh + (size_t)(k0 + j) * D + (d4 << 2));
            float vv[4] = {v4.x, v4.y, v4.z, v4.w};
#pragma unroll
            for (int i = 0; i < 4; i++) {
                int d = (d4 << 2) + i;
                __nv_bfloat16 hi = __float2bfloat16(vv[i]);
                __nv_bfloat16 lo = __float2bfloat16(vv[i] - __bfloat162float(hi));
                Vthi[d * VSTR + j] = hi;
                Vtlo[d * VSTR + j] = lo;
            }
        }
        __syncthreads();

        bool diag = (kt == qt);
        float li0 = Ls[wr + g], li1 = Ls[wr + 8 + g];

        float acc_o[8][4];
#pragma unroll
        for (int n = 0; n < 8; n++)
#pragma unroll
            for (int i = 0; i < 4; i++) acc_o[n][i] = 0.f;

#pragma unroll
        for (int kk = 0; kk < 8; kk++) {
            float uE[4], uO[4];
#pragma unroll
            for (int half = 0; half < 2; half++) {
                float* u = half ? uO : uE;
                int n = (kk << 1) + half;
                int cg = k0 + (n << 3) + (q << 1);
                u[0] = (diag && cg > gi0) ? 0.f : __expf(acc[n][0]);
                u[1] = (diag && cg + 1 > gi0) ? 0.f : __expf(acc[n][1]);
                u[2] = (diag && cg > gi1) ? 0.f : __expf(acc[n][2]);
                u[3] = (diag && cg + 1 > gi1) ? 0.f : __expf(acc[n][3]);
                __stcs((float2*)(Wh + (size_t)gi0 * S + cg),
                       make_float2(u[0] * li0, u[1] * li0));
                __stcs((float2*)(Wh + (size_t)gi1 * S + cg),
                       make_float2(u[2] * li1, u[3] * li1));
            }
            uint32_t ah[4], al[4];
            ah[0] = pk2(uE[0], uE[1]); ah[1] = pk2(uE[2], uE[3]);
            ah[2] = pk2(uO[0], uO[1]); ah[3] = pk2(uO[2], uO[3]);
            al[0] = pk2(uE[0] - __bfloat162float(__float2bfloat16(uE[0])),
                        uE[1] - __bfloat162float(__float2bfloat16(uE[1])));
            al[1] = pk2(uE[2] - __bfloat162float(__float2bfloat16(uE[2])),
                        uE[3] - __bfloat162float(__float2bfloat16(uE[3])));
            al[2] = pk2(uO[0] - __bfloat162float(__float2bfloat16(uO[0])),
                        uO[1] - __bfloat162float(__float2bfloat16(uO[1])));
            al[3] = pk2(uO[2] - __bfloat162float(__float2bfloat16(uO[2])),
                        uO[3] - __bfloat162float(__float2bfloat16(uO[3])));

#pragma unroll
            for (int dn2 = 0; dn2 < 4; dn2++) {
                uint32_t boff = (uint32_t)((((dn2 << 4) + ((L >> 4) << 3) + (L & 7)) * VSTR +
                                            (kk << 4) + (((L >> 3) & 1) << 3)) << 1);
                uint32_t bh[4], bl[4];
                ldsm4(bh, vhiB + boff);
                ldsm4(bl, vloB + boff);
                mma_bf16(acc_o[2 * dn2],     ah, &bh[0]);
                mma_bf16(acc_o[2 * dn2],     ah, &bl[0]);
                mma_bf16(acc_o[2 * dn2],     al, &bh[0]);
                mma_bf16(acc_o[2 * dn2 + 1], ah, &bh[2]);
                mma_bf16(acc_o[2 * dn2 + 1], ah, &bl[2]);
                mma_bf16(acc_o[2 * dn2 + 1], al, &bh[2]);
            }
        }

        // accumulate into thread-private Osm slots (no races: same owner)
        if (sub == 0) {
#pragma unroll
            for (int dn = 0; dn < 8; dn++) {
                int c = (dn << 3) + (q << 1);
                Osm[wr + g][c]         = acc_o[dn][0];
                Osm[wr + g][c + 1]     = acc_o[dn][1];
                Osm[wr + 8 + g][c]     = acc_o[dn][2];
                Osm[wr + 8 + g][c + 1] = acc_o[dn][3];
            }
        } else {
#pragma unroll
            for (int dn = 0; dn < 8; dn++) {
                int c = (dn << 3) + (q << 1);
                Osm[wr + g][c]         += acc_o[dn][0];
                Osm[wr + g][c + 1]     += acc_o[dn][1];
                Osm[wr + 8 + g][c]     += acc_o[dn][2];
                Osm[wr + 8 + g][c + 1] += acc_o[dn][3];
            }
        }
    }

    // raw quad-partial O (plain stores -> stays L2-resident for the reducer)
    float* P = g_part + (((size_t)(h * 16 + qt) << 2) + p) * (128 * 64);
#pragma unroll
    for (int dn = 0; dn < 8; dn++) {
        int c = (dn << 3) + (q << 1);
        *(float2*)(P + (wr + g) * 64 + c) =
            make_float2(Osm[wr + g][c], Osm[wr + g][c + 1]);
        *(float2*)(P + (wr + 8 + g) * 64 + c) =
            make_float2(Osm[wr + 8 + g][c], Osm[wr + 8 + g][c + 1]);
    }

    // last CTA for this (h, qt) reduces partials and writes O
    __threadfence();
    __syncthreads();
    int np = (qt >> 2) + 1;
    if (t == 0) {
        int old = atomicAdd(&g_cnt[(h << 4) + qt], 1);
        isLast = (old == np - 1) ? 1 : 0;
    }
    __syncthreads();
    if (isLast) {
        __threadfence();
        const float* Pb = g_part + ((size_t)(h * 16 + qt) << 2) * (128 * 64);
        float* Oh = O + (size_t)h * S * D;
        for (int f = t; f < 2048; f += 256) {
            float4 s = make_float4(0.f, 0.f, 0.f, 0.f);
            for (int pp = 0; pp < np; pp++) {
                float4 v = __ldcg((const float4*)(Pb + (size_t)pp * (128 * 64) + (f << 2)));
                s.x += v.x; s.y += v.y; s.z += v.z; s.w += v.w;
            }
            float li = Ls[f >> 4];
            *(float4*)(Oh + (size_t)q0 * D + (f << 2)) =
                make_float4(s.x * li, s.y * li, s.z * li, s.w * li);
        }
    }
}

// ---------------------------------------------------------------------------
// fallback (output-only branch)
// ---------------------------------------------------------------------------
__global__ void fallback_kernel(const float* __restrict__ Q,
                                const float* __restrict__ K,
                                const float* __restrict__ V,
                                float* __restrict__ O) {
    int i = blockIdx.x, h = blockIdx.y;
    const float* Qh = Q + (size_t)h * S * D;
    const float* Kh = K + (size_t)h * S * D;
    const float* Vh = V + (size_t)h * S * D;
    float* Oh = O + (size_t)h * S * D;
    __shared__ float p[S];
    __shared__ float qsh[D];
    __shared__ float red[64];
    int t = threadIdx.x;
    qsh[t] = Qh[(size_t)i * D + t];
    __syncthreads();
    float lsum = 0.f;
    for (int j = t; j <= i; j += 64) {
        const float* kr = Kh + (size_t)j * D;
        float s = 0.f;
#pragma unroll 16
        for (int d = 0; d < D; d++) s = fmaf(qsh[d], kr[d], s);
        float e = __expf(s * SCALE);
        p[j] = e; lsum += e;
    }
    red[t] = lsum; __syncthreads();
    for (int s2 = 32; s2 > 0; s2 >>= 1) { if (t < s2) red[t] += red[t + s2]; __syncthreads(); }
    float inv = 1.0f / red[0];
    __syncthreads();
    float o = 0.f;
    for (int j = 0; j <= i; j++) o = fmaf(p[j], Vh[(size_t)j * D + t], o);
    Oh[(size_t)i * D + t] = o * inv;
}

// ---------------------------------------------------------------------------
extern "C" void kernel_launch(void* const* d_in, const int* in_sizes, int n_in,
                              void* d_out, int out_size) {
    const float* Q = (const float*)d_in[0];
    const float* K = (const float*)d_in[1];
    const float* V = (const float*)d_in[2];
    float* out = (float*)d_out;

    const long long O_ELEMS = (long long)NH * S * D;
    const long long W_ELEMS = (long long)NH * S * S;

    const int SMEM_TILES = 4 * 128 * STR * 2;   // 73728 B
    cudaFuncSetAttribute(stats_mma, cudaFuncAttributeMaxDynamicSharedMemorySize, SMEM_TILES);
    cudaFuncSetAttribute(emit_mma,  cudaFuncAttributeMaxDynamicSharedMemorySize, SMEM_TILES);

    if ((long long)out_size >= O_ELEMS + W_ELEMS) {
        float* W = out + O_ELEMS;
        stats_mma<<<dim3(8, 16, 32), 256, SMEM_TILES>>>(Q, K, W);
        emit_mma<<<dim3(4, 16, 32), 256, SMEM_TILES>>>(Q, K, V, W, out);
    } else if ((long long)out_size == W_ELEMS) {
        float* W = out;
        float* Oscratch;
        cudaGetSymbolAddress((void**)&Oscratch, g_Oscratch);
        stats_mma<<<dim3(8, 16, 32), 256, SMEM_TILES>>>(Q, K, W);
        emit_mma<<<dim3(4, 16, 32), 256, SMEM_TILES>>>(Q, K, V, W, Oscratch);
    } else {
        fallback_kernel<<<dim3(S, NH), 64>>>(Q, K, V, out);
    }
}

// round 13
// speedup vs baseline: 1.2014x; 1.1358x over previous
#include <cuda_runtime.h>
#include <cuda_bf16.h>
#include <math.h>
#include <stdint.h>

#define S 2048
#define D 64
#define NH 32
#define SCALE 0.125f
#define STR 72            // smem row stride in bf16 (64 data + 8 pad)

// per-(head, 128-wide k-tile, row) partial sums of exp(s)
__device__ float g_stats[(size_t)NH * 16 * S];
// split-K partial O over 512-wide k-quads: [h][qt][p<4][128*64]
__device__ float g_part[(size_t)NH * 16 * 4 * 128 * 64];
// completion counters per (h, qt)
__device__ int g_cnt[NH * 16];
// scratch O for the weights-only branch
__device__ float g_Oscratch[(size_t)NH * S * D];

// ------------------------------ helpers -----------------------------------
__device__ __forceinline__ uint32_t smem_u32(const void* p) {
    return (uint32_t)__cvta_generic_to_shared(p);
}
__device__ __forceinline__ void ldsm4(uint32_t* r, uint32_t addr) {
    asm volatile("ldmatrix.sync.aligned.m8n8.x4.shared.b16 {%0,%1,%2,%3}, [%4];"
                 : "=r"(r[0]), "=r"(r[1]), "=r"(r[2]), "=r"(r[3]) : "r"(addr));
}
__device__ __forceinline__ void ldsm4t(uint32_t* r, uint32_t addr) {
    asm volatile("ldmatrix.sync.aligned.m8n8.x4.trans.shared.b16 {%0,%1,%2,%3}, [%4];"
                 : "=r"(r[0]), "=r"(r[1]), "=r"(r[2]), "=r"(r[3]) : "r"(addr));
}
__device__ __forceinline__ void ldsm2(uint32_t* r, uint32_t addr) {
    asm volatile("ldmatrix.sync.aligned.m8n8.x2.shared.b16 {%0,%1}, [%2];"
                 : "=r"(r[0]), "=r"(r[1]) : "r"(addr));
}
__device__ __forceinline__ void mma_bf16(float* c, const uint32_t* a, const uint32_t* b) {
    asm volatile("mma.sync.aligned.m16n8k16.row.col.f32.bf16.bf16.f32 "
                 "{%0,%1,%2,%3},{%4,%5,%6,%7},{%8,%9},{%0,%1,%2,%3};"
                 : "+f"(c[0]), "+f"(c[1]), "+f"(c[2]), "+f"(c[3])
                 : "r"(a[0]), "r"(a[1]), "r"(a[2]), "r"(a[3]), "r"(b[0]), "r"(b[1]));
}
__device__ __forceinline__ void split4(__nv_bfloat16* hi, __nv_bfloat16* lo,
                                       int off, float4 v) {
    __nv_bfloat16 h0 = __float2bfloat16(v.x), h1 = __float2bfloat16(v.y);
    __nv_bfloat16 h2 = __float2bfloat16(v.z), h3 = __float2bfloat16(v.w);
    __nv_bfloat16 l0 = __float2bfloat16(v.x - __bfloat162float(h0));
    __nv_bfloat16 l1 = __float2bfloat16(v.y - __bfloat162float(h1));
    __nv_bfloat16 l2 = __float2bfloat16(v.z - __bfloat162float(h2));
    __nv_bfloat16 l3 = __float2bfloat16(v.w - __bfloat162float(h3));
    uint2 hv = make_uint2((uint32_t)__bfloat16_as_ushort(h0) | ((uint32_t)__bfloat16_as_ushort(h1) << 16),
                          (uint32_t)__bfloat16_as_ushort(h2) | ((uint32_t)__bfloat16_as_ushort(h3) << 16));
    uint2 lv = make_uint2((uint32_t)__bfloat16_as_ushort(l0) | ((uint32_t)__bfloat16_as_ushort(l1) << 16),
                          (uint32_t)__bfloat16_as_ushort(l2) | ((uint32_t)__bfloat16_as_ushort(l3) << 16));
    *(uint2*)(hi + off) = hv;
    *(uint2*)(lo + off) = lv;
}
__device__ __forceinline__ uint32_t pk2(float a, float b) {
    __nv_bfloat162 h = __floats2bfloat162_rn(a, b);
    return *(uint32_t*)&h;
}

__device__ __forceinline__ void stage_q(const float* Qh, int q0, int t,
                                        __nv_bfloat16* Qhi, __nv_bfloat16* Qlo) {
    for (int e = t; e < 128 * 16; e += 256) {
        int r = e >> 4, c4 = e & 15;
        float4 q4 = *(const float4*)(Qh + (size_t)(q0 + r) * D + (c4 << 2));
        q4.x *= SCALE; q4.y *= SCALE; q4.z *= SCALE; q4.w *= SCALE;
        split4(Qhi, Qlo, r * STR + (c4 << 2), q4);
    }
}
// row-major split staging of a 128x64 fp32 block (used for K and V tiles)
__device__ __forceinline__ void stage_k(const float* Kh, int k0, int t,
                                        __nv_bfloat16* Khi, __nv_bfloat16* Klo) {
    for (int e = t; e < 128 * 16; e += 256) {
        int r = e >> 4, c4 = e & 15;
        float4 k4 = *(const float4*)(Kh + (size_t)(k0 + r) * D + (c4 << 2));
        split4(Khi, Klo, r * STR + (c4 << 2), k4);
    }
}

// full-precision QK^T (3 MMA), ldsm4-paired B (emit)
__device__ __forceinline__ void qk_mma8(uint32_t qhiB, uint32_t qloB,
                                        uint32_t khiB, uint32_t kloB,
                                        int wr, int L, float acc[16][4]) {
#pragma unroll
    for (int kk = 0; kk < 4; kk++) {
        uint32_t ah[4], al[4];
        uint32_t aoff = (uint32_t)(((wr + (L & 15)) * STR + (kk << 4) + ((L >> 4) << 3)) << 1);
        ldsm4(ah, qhiB + aoff);
        ldsm4(al, qloB + aoff);
#pragma unroll
        for (int n2 = 0; n2 < 8; n2++) {
            uint32_t boff = (uint32_t)((((n2 << 4) + ((L >> 4) << 3) + (L & 7)) * STR +
                                        (kk << 4) + (((L >> 3) & 1) << 3)) << 1);
            uint32_t bh[4], bl[4];
            ldsm4(bh, khiB + boff);
            ldsm4(bl, kloB + boff);
            mma_bf16(acc[2 * n2],     ah, &bh[0]);
            mma_bf16(acc[2 * n2],     ah, &bl[0]);
            mma_bf16(acc[2 * n2],     al, &bh[0]);
            mma_bf16(acc[2 * n2 + 1], ah, &bh[2]);
            mma_bf16(acc[2 * n2 + 1], ah, &bl[2]);
            mma_bf16(acc[2 * n2 + 1], al, &bh[2]);
        }
    }
}

// ---------------------------------------------------------------------------
// K1: stats — full-precision QK per 256-wide k-pair, rowsums -> g_stats.
// Masked-band CTAs zero-fill W; p==0 CTAs also reset the emit counters.
// ---------------------------------------------------------------------------
__global__ __launch_bounds__(256, 3)
void stats_mma(const float* __restrict__ Q, const float* __restrict__ Km,
               float* __restrict__ W) {
    int p = blockIdx.x, qt = 15 - blockIdx.y, h = blockIdx.z;
    int kt0 = p << 1;
    int q0 = qt << 7;
    int t = threadIdx.x;
    float* Wh = W + (size_t)h * S * S;

    if (p == 0 && t == 0) g_cnt[(h << 4) + qt] = 0;   // reset emit counter

    if (kt0 > qt) {                      // masked band: final W is 0
        float4 z = make_float4(0.f, 0.f, 0.f, 0.f);
        int c0 = kt0 << 7;
        for (int e = t; e < 128 * 64; e += 256) {
            int r = e >> 6, c4 = e & 63;
            __stcs((float4*)(Wh + (size_t)(q0 + r) * S + c0 + (c4 << 2)), z);
        }
        return;
    }

    extern __shared__ char smraw[];
    __nv_bfloat16* Qhi = (__nv_bfloat16*)smraw;
    __nv_bfloat16* Qlo = Qhi + 128 * STR;
    __nv_bfloat16* Khi = Qlo + 128 * STR;
    __nv_bfloat16* Klo = Khi + 128 * STR;

    stage_q(Q + (size_t)h * S * D, q0, t, Qhi, Qlo);

    const float* Kh = Km + (size_t)h * S * D;
    int w = t >> 5, L = t & 31;
    int wr = w << 4;
    int g = L >> 2, q = L & 3;
    int gi0 = q0 + wr + g, gi1 = gi0 + 8;
    uint32_t qhiB = smem_u32(Qhi), qloB = smem_u32(Qlo);
    uint32_t khiB = smem_u32(Khi), kloB = smem_u32(Klo);

#pragma unroll 1
    for (int sub = 0; sub < 2; sub++) {
        int kt = kt0 + sub;
        if (kt > qt) break;
        int k0 = kt << 7;
        __syncthreads();
        stage_k(Kh, k0, t, Khi, Klo);
        __syncthreads();

        uint32_t ah[4][4], al[4][4];
#pragma unroll
        for (int kk = 0; kk < 4; kk++) {
            uint32_t aoff = (uint32_t)(((wr + (L & 15)) * STR + (kk << 4) + ((L >> 4) << 3)) << 1);
            ldsm4(ah[kk], qhiB + aoff);
            ldsm4(al[kk], qloB + aoff);
        }

        float s0 = 0.f, s1 = 0.f;
        bool diag = (kt == qt);
#pragma unroll
        for (int n = 0; n < 16; n++) {
            float acc[4] = {0.f, 0.f, 0.f, 0.f};
#pragma unroll
            for (int kk = 0; kk < 4; kk++) {
                uint32_t boff = (uint32_t)((((n << 3) + (L & 7)) * STR +
                                            (kk << 4) + (((L >> 3) & 1) << 3)) << 1);
                uint32_t bh[2], bl[2];
                ldsm2(bh, khiB + boff);
                ldsm2(bl, kloB + boff);
                mma_bf16(acc, ah[kk], bh);
                mma_bf16(acc, ah[kk], bl);
                mma_bf16(acc, al[kk], bh);
            }
            if (diag) {
                int cg = k0 + (n << 3) + (q << 1);
                s0 += ((cg > gi0) ? 0.f : __expf(acc[0])) +
                      ((cg + 1 > gi0) ? 0.f : __expf(acc[1]));
                s1 += ((cg > gi1) ? 0.f : __expf(acc[2])) +
                      ((cg + 1 > gi1) ? 0.f : __expf(acc[3]));
            } else {
                s0 += __expf(acc[0]) + __expf(acc[1]);
                s1 += __expf(acc[2]) + __expf(acc[3]);
            }
        }
        s0 += __shfl_xor_sync(0xffffffffu, s0, 1);
        s0 += __shfl_xor_sync(0xffffffffu, s0, 2);
        s1 += __shfl_xor_sync(0xffffffffu, s1, 1);
        s1 += __shfl_xor_sync(0xffffffffu, s1, 2);
        if (q == 0) {
            size_t sb = (size_t)(h * 16 + kt) * S;
            g_stats[sb + gi0] = s0;
            g_stats[sb + gi1] = s1;
        }
    }

    // odd-straddle: qt even & kt0 == qt -> tile kt0+1 is fully masked
    if (kt0 == qt && kt0 + 1 <= 15) {
        float4 z = make_float4(0.f, 0.f, 0.f, 0.f);
        int c0 = (kt0 + 1) << 7;
        for (int e = t; e < 128 * 32; e += 256) {
            int r = e >> 5, c4 = e & 31;
            __stcs((float4*)(Wh + (size_t)(q0 + r) * S + c0 + (c4 << 2)), z);
        }
    }
}

// ---------------------------------------------------------------------------
// K2: emit — per (h, qt, 512-wide k-quad): recompute s (full precision),
// write final W = exp(s)*Linv once, fused PV with ldmatrix.trans V fragments;
// quad-partial O -> g_part; last CTA per (h, qt) reduces and writes O.
// ---------------------------------------------------------------------------
__global__ __launch_bounds__(256, 2)
void emit_mma(const float* __restrict__ Q, const float* __restrict__ Km,
              const float* __restrict__ V, float* __restrict__ W,
              float* __restrict__ O) {
    int p = blockIdx.x, qt = 15 - blockIdx.y, h = blockIdx.z;
    int kt0 = p << 2;
    if (kt0 > qt) return;                // zero-fill done in stats_mma
    float* Wh = W + (size_t)h * S * S;
    int q0 = qt << 7;
    int t = threadIdx.x;

    extern __shared__ char smraw[];
    __nv_bfloat16* Qhi = (__nv_bfloat16*)smraw;
    __nv_bfloat16* Qlo = Qhi + 128 * STR;
    __nv_bfloat16* Khi = Qlo + 128 * STR;
    __nv_bfloat16* Klo = Khi + 128 * STR;
    __nv_bfloat16* Vhi = Khi;            // reused after QK mma (row-major now)
    __nv_bfloat16* Vlo = Klo;
    __shared__ float Ls[128];
    __shared__ float Osm[128][68];
    __shared__ int isLast;

    const float* Vh = V + (size_t)h * S * D;

    if (t < 128) {
        float Lsum = 0.f;
        for (int k2 = 0; k2 <= qt; k2++)
            Lsum += g_stats[(size_t)(h * 16 + k2) * S + q0 + t];
        Ls[t] = 1.f / Lsum;
    }
    stage_q(Q + (size_t)h * S * D, q0, t, Qhi, Qlo);

    int w = t >> 5, L = t & 31;
    int wr = w << 4;
    int g = L >> 2, q = L & 3;
    int gi0 = q0 + wr + g, gi1 = gi0 + 8;
    uint32_t vhiB = smem_u32(Vhi), vloB = smem_u32(Vlo);

#pragma unroll 1
    for (int sub = 0; sub < 4; sub++) {
        int kt = kt0 + sub;
        if (kt > qt) break;
        int k0 = kt << 7;
        __syncthreads();
        stage_k(Km + (size_t)h * S * D, k0, t, Khi, Klo);
        __syncthreads();

        float acc[16][4];
#pragma unroll
        for (int n = 0; n < 16; n++)
#pragma unroll
            for (int i = 0; i < 4; i++) acc[n][i] = 0.f;
        qk_mma8(smem_u32(Qhi), smem_u32(Qlo), smem_u32(Khi), smem_u32(Klo), wr, L, acc);
        __syncthreads();

        // stage V tile row-major (hi/lo split), replaces scalar transpose
        stage_k(Vh, k0, t, Vhi, Vlo);
        __syncthreads();

        bool diag = (kt == qt);
        float li0 = Ls[wr + g], li1 = Ls[wr + 8 + g];

        float acc_o[8][4];
#pragma unroll
        for (int n = 0; n < 8; n++)
#pragma unroll
            for (int i = 0; i < 4; i++) acc_o[n][i] = 0.f;

#pragma unroll
        for (int kk = 0; kk < 8; kk++) {
            float uE[4], uO[4];
#pragma unroll
            for (int half = 0; half < 2; half++) {
                float* u = half ? uO : uE;
                int n = (kk << 1) + half;
                int cg = k0 + (n << 3) + (q << 1);
                u[0] = (diag && cg > gi0) ? 0.f : __expf(acc[n][0]);
                u[1] = (diag && cg + 1 > gi0) ? 0.f : __expf(acc[n][1]);
                u[2] = (diag && cg > gi1) ? 0.f : __expf(acc[n][2]);
                u[3] = (diag && cg + 1 > gi1) ? 0.f : __expf(acc[n][3]);
                __stcs((float2*)(Wh + (size_t)gi0 * S + cg),
                       make_float2(u[0] * li0, u[1] * li0));
                __stcs((float2*)(Wh + (size_t)gi1 * S + cg),
                       make_float2(u[2] * li1, u[3] * li1));
            }
            uint32_t ah[4], al[4];
            ah[0] = pk2(uE[0], uE[1]); ah[1] = pk2(uE[2], uE[3]);
            ah[2] = pk2(uO[0], uO[1]); ah[3] = pk2(uO[2], uO[3]);
            al[0] = pk2(uE[0] - __bfloat162float(__float2bfloat16(uE[0])),
                        uE[1] - __bfloat162float(__float2bfloat16(uE[1])));
            al[1] = pk2(uE[2] - __bfloat162float(__float2bfloat16(uE[2])),
                        uE[3] - __bfloat162float(__float2bfloat16(uE[3])));
            al[2] = pk2(uO[0] - __bfloat162float(__float2bfloat16(uO[0])),
                        uO[1] - __bfloat162float(__float2bfloat16(uO[1])));
            al[3] = pk2(uO[2] - __bfloat162float(__float2bfloat16(uO[2])),
                        uO[3] - __bfloat162float(__float2bfloat16(uO[3])));

            // B fragments from row-major V via ldmatrix.trans:
            // lane: row j = kk*16 + (L&15), col d = dn2*16 + ((L>>4)<<3)
#pragma unroll
            for (int dn2 = 0; dn2 < 4; dn2++) {
                uint32_t boff = (uint32_t)((((kk << 4) + (L & 15)) * STR +
                                            (dn2 << 4) + (((L >> 4) & 1) << 3)) << 1);
                uint32_t bh[4], bl[4];
                ldsm4t(bh, vhiB + boff);
                ldsm4t(bl, vloB + boff);
                mma_bf16(acc_o[2 * dn2],     ah, &bh[0]);
                mma_bf16(acc_o[2 * dn2],     ah, &bl[0]);
                mma_bf16(acc_o[2 * dn2],     al, &bh[0]);
                mma_bf16(acc_o[2 * dn2 + 1], ah, &bh[2]);
                mma_bf16(acc_o[2 * dn2 + 1], ah, &bl[2]);
                mma_bf16(acc_o[2 * dn2 + 1], al, &bh[2]);
            }
        }

        // accumulate into thread-private Osm slots (no races: same owner)
        if (sub == 0) {
#pragma unroll
            for (int dn = 0; dn < 8; dn++) {
                int c = (dn << 3) + (q << 1);
                Osm[wr + g][c]         = acc_o[dn][0];
                Osm[wr + g][c + 1]     = acc_o[dn][1];
                Osm[wr + 8 + g][c]     = acc_o[dn][2];
                Osm[wr + 8 + g][c + 1] = acc_o[dn][3];
            }
        } else {
#pragma unroll
            for (int dn = 0; dn < 8; dn++) {
                int c = (dn << 3) + (q << 1);
                Osm[wr + g][c]         += acc_o[dn][0];
                Osm[wr + g][c + 1]     += acc_o[dn][1];
                Osm[wr + 8 + g][c]     += acc_o[dn][2];
                Osm[wr + 8 + g][c + 1] += acc_o[dn][3];
            }
        }
    }

    // raw quad-partial O (plain stores -> stays L2-resident for the reducer)
    float* P = g_part + (((size_t)(h * 16 + qt) << 2) + p) * (128 * 64);
#pragma unroll
    for (int dn = 0; dn < 8; dn++) {
        int c = (dn << 3) + (q << 1);
        *(float2*)(P + (wr + g) * 64 + c) =
            make_float2(Osm[wr + g][c], Osm[wr + g][c + 1]);
        *(float2*)(P + (wr + 8 + g) * 64 + c) =
            make_float2(Osm[wr + 8 + g][c], Osm[wr + 8 + g][c + 1]);
    }

    // last CTA for this (h, qt) reduces partials and writes O
    __threadfence();
    __syncthreads();
    int np = (qt >> 2) + 1;
    if (t == 0) {
        int old = atomicAdd(&g_cnt[(h << 4) + qt], 1);
        isLast = (old == np - 1) ? 1 : 0;
    }
    __syncthreads();
    if (isLast) {
        __threadfence();
        const float* Pb = g_part + ((size_t)(h * 16 + qt) << 2) * (128 * 64);
        float* Oh = O + (size_t)h * S * D;
        for (int f = t; f < 2048; f += 256) {
            float4 s = make_float4(0.f, 0.f, 0.f, 0.f);
            for (int pp = 0; pp < np; pp++) {
                float4 v = __ldcg((const float4*)(Pb + (size_t)pp * (128 * 64) + (f << 2)));
                s.x += v.x; s.y += v.y; s.z += v.z; s.w += v.w;
            }
            float li = Ls[f >> 4];
            *(float4*)(Oh + (size_t)q0 * D + (f << 2)) =
                make_float4(s.x * li, s.y * li, s.z * li, s.w * li);
        }
    }
}

// ---------------------------------------------------------------------------
// fallback (output-only branch)
// ---------------------------------------------------------------------------
__global__ void fallback_kernel(const float* __restrict__ Q,
                                const float* __restrict__ K,
                                const float* __restrict__ V,
                                float* __restrict__ O) {
    int i = blockIdx.x, h = blockIdx.y;
    const float* Qh = Q + (size_t)h * S * D;
    const float* Kh = K + (size_t)h * S * D;
    const float* Vh = V + (size_t)h * S * D;
    float* Oh = O + (size_t)h * S * D;
    __shared__ float p[S];
    __shared__ float qsh[D];
    __shared__ float red[64];
    int t = threadIdx.x;
    qsh[t] = Qh[(size_t)i * D + t];
    __syncthreads();
    float lsum = 0.f;
    for (int j = t; j <= i; j += 64) {
        const float* kr = Kh + (size_t)j * D;
        float s = 0.f;
#pragma unroll 16
        for (int d = 0; d < D; d++) s = fmaf(qsh[d], kr[d], s);
        float e = __expf(s * SCALE);
        p[j] = e; lsum += e;
    }
    red[t] = lsum; __syncthreads();
    for (int s2 = 32; s2 > 0; s2 >>= 1) { if (t < s2) red[t] += red[t + s2]; __syncthreads(); }
    float inv = 1.0f / red[0];
    __syncthreads();
    float o = 0.f;
    for (int j = 0; j <= i; j++) o = fmaf(p[j], Vh[(size_t)j * D + t], o);
    Oh[(size_t)i * D + t] = o * inv;
}

// ---------------------------------------------------------------------------
extern "C" void kernel_launch(void* const* d_in, const int* in_sizes, int n_in,
                              void* d_out, int out_size) {
    const float* Q = (const float*)d_in[0];
    const float* K = (const float*)d_in[1];
    const float* V = (const float*)d_in[2];
    float* out = (float*)d_out;

    const long long O_ELEMS = (long long)NH * S * D;
    const long long W_ELEMS = (long long)NH * S * S;

    const int SMEM_TILES = 4 * 128 * STR * 2;   // 73728 B
    cudaFuncSetAttribute(stats_mma, cudaFuncAttributeMaxDynamicSharedMemorySize, SMEM_TILES);
    cudaFuncSetAttribute(emit_mma,  cudaFuncAttributeMaxDynamicSharedMemorySize, SMEM_TILES);

    if ((long long)out_size >= O_ELEMS + W_ELEMS) {
        float* W = out + O_ELEMS;
        stats_mma<<<dim3(8, 16, 32), 256, SMEM_TILES>>>(Q, K, W);
        emit_mma<<<dim3(4, 16, 32), 256, SMEM_TILES>>>(Q, K, V, W, out);
    } else if ((long long)out_size == W_ELEMS) {
        float* W = out;
        float* Oscratch;
        cudaGetSymbolAddress((void**)&Oscratch, g_Oscratch);
        stats_mma<<<dim3(8, 16, 32), 256, SMEM_TILES>>>(Q, K, W);
        emit_mma<<<dim3(4, 16, 32), 256, SMEM_TILES>>>(Q, K, V, W, Oscratch);
    } else {
        fallback_kernel<<<dim3(S, NH), 64>>>(Q, K, V, out);
    }
}